// round 3
// baseline (speedup 1.0000x reference)
#include <cuda_runtime.h>
#include <cstdint>

#define B_     256
#define C_     2048
#define K_     18
#define HW_    192
#define TPB    256
#define CPT    2
#define CTILE  (TPB*CPT)          // 512 c-rows per block
#define CHUNK  8                  // hw positions staged per phase
#define NCH    (HW_/CHUNK)        // 24 phases
#define FSTRIDE 12                // feat row stride in words (8 data + 4 pad)
#define MSTRIDE 20                // transposed mask row stride (18 k + 2 pad)

#define SM_MASK_WORDS (HW_*MSTRIDE)            // 3840
#define SM_FEAT_WORDS (CTILE*FSTRIDE)          // 6144
#define SM_TOTAL_BYTES ((SM_MASK_WORDS + 2*SM_FEAT_WORDS)*4)   // 64512

// Packed fp32x2 FMA (only reachable via PTX; ptxas never auto-fuses).
__device__ __forceinline__ void ffma2(float2& acc, float2 m, float2 v) {
    unsigned long long a  = *reinterpret_cast<unsigned long long*>(&acc);
    unsigned long long mm = *reinterpret_cast<unsigned long long*>(&m);
    unsigned long long vv = *reinterpret_cast<unsigned long long*>(&v);
    asm("fma.rn.f32x2 %0, %1, %2, %0;" : "+l"(a) : "l"(mm), "l"(vv));
    acc = *reinterpret_cast<float2*>(&a);
}

__device__ __forceinline__ uint32_t s2u(const void* p) {
    uint32_t a;
    asm("{ .reg .u64 t; cvta.to.shared.u64 t, %1; cvt.u32.u64 %0, t; }"
        : "=r"(a) : "l"(p));
    return a;
}
__device__ __forceinline__ void cpasync16(uint32_t s, const void* g) {
    asm volatile("cp.async.cg.shared.global [%0], [%1], 16;" :: "r"(s), "l"(g));
}
__device__ __forceinline__ void cp_commit() {
    asm volatile("cp.async.commit_group;" ::: "memory");
}
template <int N>
__device__ __forceinline__ void cp_wait() {
    asm volatile("cp.async.wait_group %0;" :: "n"(N) : "memory");
}

extern __shared__ float smem[];

__global__ __launch_bounds__(TPB, 3)
void pgfa_kernel(const float* __restrict__ feat,
                 const float* __restrict__ masks,
                 const float* __restrict__ pgf,
                 float* __restrict__ out)
{
    float* s_mt = smem;                         // transposed masks [HW_][MSTRIDE]
    float* s_f0 = smem + SM_MASK_WORDS;         // feat buffer 0
    float* s_f1 = s_f0 + SM_FEAT_WORDS;         // feat buffer 1

    const int b     = blockIdx.y;
    const int tid   = threadIdx.x;
    const int cbase = blockIdx.x * CTILE;

    // ---- stage masks[b], transposed to [hw][k] ----
    {
        const float* msrc = masks + (size_t)b * K_ * HW_;
        for (int i = tid; i < K_ * HW_; i += TPB) {
            int k  = i / HW_;
            int hw = i - k * HW_;        // consecutive tid -> consecutive hw (coalesced LDG)
            s_mt[hw * MSTRIDE + k] = msrc[i];
        }
    }

    const float* frow_base = feat + ((size_t)b * C_ + cbase) * HW_;

    // cp.async chunk ch into dst: 512 rows x 8 floats = 1024 float4, 4/thread
    auto issue_chunk = [&](float* dst, int ch) {
        uint32_t sbase = s2u(dst);
        #pragma unroll
        for (int q = 0; q < 4; q++) {
            int flat = q * TPB + tid;           // 0..1023
            int row  = flat >> 1;
            int o    = flat & 1;
            const float* g = frow_base + (size_t)row * HW_ + ch * CHUNK + o * 4;
            uint32_t s = sbase + (row * FSTRIDE + o * 4) * 4;
            cpasync16(s, g);
        }
        cp_commit();
    };

    // k-paired accumulators: acc[j][kk] = (sum for k=2kk, sum for k=2kk+1)
    float2 acc[CPT][K_/2];
    #pragma unroll
    for (int j = 0; j < CPT; j++)
        #pragma unroll
        for (int kk = 0; kk < K_/2; kk++) acc[j][kk] = make_float2(0.f, 0.f);

    issue_chunk(s_f0, 0);

    #pragma unroll 1
    for (int ch = 0; ch < NCH; ch++) {
        float* cur = (ch & 1) ? s_f1 : s_f0;
        float* nxt = (ch & 1) ? s_f0 : s_f1;

        if (ch + 1 < NCH) { issue_chunk(nxt, ch + 1); cp_wait<1>(); }
        else              { cp_wait<0>(); }
        __syncthreads();   // chunk ch (and masks on first iter) visible

        #pragma unroll
        for (int o = 0; o < 2; o++) {          // two hw-quads per chunk
            float4 v[CPT];
            #pragma unroll
            for (int j = 0; j < CPT; j++) {
                int row = tid + j * TPB;
                v[j] = *reinterpret_cast<const float4*>(cur + row * FSTRIDE + o * 4);
            }
            #pragma unroll
            for (int h = 0; h < 4; h++) {      // scalar hw within quad
                const float* mrow = s_mt + (ch * CHUNK + o * 4 + h) * MSTRIDE;
                float vh[CPT];
                vh[0] = (h == 0) ? v[0].x : (h == 1) ? v[0].y : (h == 2) ? v[0].z : v[0].w;
                vh[1] = (h == 0) ? v[1].x : (h == 1) ? v[1].y : (h == 2) ? v[1].z : v[1].w;
                #pragma unroll
                for (int g = 0; g < 4; g++) {  // k = 4g..4g+3 (broadcast LDS.128)
                    float4 m4 = *reinterpret_cast<const float4*>(mrow + 4 * g);
                    #pragma unroll
                    for (int j = 0; j < CPT; j++) {
                        ffma2(acc[j][2*g],   make_float2(m4.x, m4.y), make_float2(vh[j], vh[j]));
                        ffma2(acc[j][2*g+1], make_float2(m4.z, m4.w), make_float2(vh[j], vh[j]));
                    }
                }
                float2 m2 = *reinterpret_cast<const float2*>(mrow + 16);   // k=16,17
                #pragma unroll
                for (int j = 0; j < CPT; j++)
                    ffma2(acc[j][8], m2, make_float2(vh[j], vh[j]));
            }
        }
        __syncthreads();   // reads of cur done before it is refilled
    }

    // ---- epilogue: mean, max over k, write both halves ----
    const float inv = 1.0f / (float)HW_;
    #pragma unroll
    for (int j = 0; j < CPT; j++) {
        const int c = cbase + tid + j * TPB;
        float mx = -3.402823466e+38f;
        #pragma unroll
        for (int kk = 0; kk < K_/2; kk++)
            mx = fmaxf(mx, fmaxf(acc[j][kk].x, acc[j][kk].y));
        const size_t orow = (size_t)b * (2 * C_);
        out[orow + C_ + c] = mx * inv;
        out[orow + c]      = pgf[(size_t)b * C_ + c];
    }
}

extern "C" void kernel_launch(void* const* d_in, const int* in_sizes, int n_in,
                              void* d_out, int out_size)
{
    const float* feat  = (const float*)d_in[0];
    const float* masks = (const float*)d_in[1];
    const float* pgf   = (const float*)d_in[2];
    float*       out   = (float*)d_out;

    cudaFuncSetAttribute(pgfa_kernel,
                         cudaFuncAttributeMaxDynamicSharedMemorySize,
                         SM_TOTAL_BYTES);

    dim3 grid(C_ / CTILE, B_);   // (4, 256)
    pgfa_kernel<<<grid, TPB, SM_TOTAL_BYTES>>>(feat, masks, pgf, out);
}

// round 4
// speedup vs baseline: 1.0278x; 1.0278x over previous
#include <cuda_runtime.h>
#include <cstdint>

#define B_     256
#define C_     2048
#define K_     18
#define HW_    192
#define TPB    256
#define CPT    2
#define CTILE  (TPB*CPT)          // 512 c-rows per block
#define CHUNK  8                  // hw positions per phase
#define NCH    (HW_/CHUNK)        // 24 phases
#define NBUF   4                  // pipeline depth (3 chunks in flight)
#define FSTRIDE 12                // feat row stride (8 data + 4 pad), 12%8==4 -> conflict-free
#define SM_MASK_WORDS (K_*HW_)                 // 3456
#define SM_FEAT_WORDS (CTILE*FSTRIDE)          // 6144
#define SM_TOTAL_BYTES ((SM_MASK_WORDS + NBUF*SM_FEAT_WORDS)*4)   // 112128

// Packed fp32x2 FMA (PTX-only; ptxas never auto-fuses).
__device__ __forceinline__ void ffma2(float2& acc, float2 m, float2 v) {
    unsigned long long a  = *reinterpret_cast<unsigned long long*>(&acc);
    unsigned long long mm = *reinterpret_cast<unsigned long long*>(&m);
    unsigned long long vv = *reinterpret_cast<unsigned long long*>(&v);
    asm("fma.rn.f32x2 %0, %1, %2, %0;" : "+l"(a) : "l"(mm), "l"(vv));
    acc = *reinterpret_cast<float2*>(&a);
}

__device__ __forceinline__ uint32_t s2u(const void* p) {
    uint32_t a;
    asm("{ .reg .u64 t; cvta.to.shared.u64 t, %1; cvt.u32.u64 %0, t; }"
        : "=r"(a) : "l"(p));
    return a;
}
__device__ __forceinline__ void cpasync16(uint32_t s, const void* g) {
    asm volatile("cp.async.cg.shared.global [%0], [%1], 16;" :: "r"(s), "l"(g));
}
__device__ __forceinline__ void cp_commit() {
    asm volatile("cp.async.commit_group;" ::: "memory");
}
template <int N>
__device__ __forceinline__ void cp_wait() {
    asm volatile("cp.async.wait_group %0;" :: "n"(N) : "memory");
}

extern __shared__ float smem[];

__global__ __launch_bounds__(TPB, 2)
void pgfa_kernel(const float* __restrict__ feat,
                 const float* __restrict__ masks,
                 const float* __restrict__ pgf,
                 float* __restrict__ out)
{
    float* s_m = smem;                          // masks [K_][HW_]
    float* s_f = smem + SM_MASK_WORDS;          // NBUF feat buffers

    const int b     = blockIdx.y;
    const int tid   = threadIdx.x;
    const int cbase = blockIdx.x * CTILE;

    // ---- stage masks[b] (coalesced float4) ----
    {
        const float4* msrc = reinterpret_cast<const float4*>(masks + (size_t)b * K_ * HW_);
        float4*       mdst = reinterpret_cast<float4*>(s_m);
        #pragma unroll
        for (int i = tid; i < K_ * HW_ / 4; i += TPB) mdst[i] = msrc[i];
    }

    const float* frow_base = feat + ((size_t)b * C_ + cbase) * HW_;
    const uint32_t sfbase = s2u(s_f);

    // cp.async chunk ch into buffer ch%NBUF: 512 rows x 8 floats = 1024 float4, 4/thread
    auto issue_chunk = [&](int ch) {
        uint32_t sbase = sfbase + (uint32_t)(ch & (NBUF - 1)) * (SM_FEAT_WORDS * 4);
        #pragma unroll
        for (int q = 0; q < 4; q++) {
            int flat = q * TPB + tid;           // 0..1023
            int row  = flat >> 1;
            int o    = flat & 1;
            const float* g = frow_base + (size_t)row * HW_ + ch * CHUNK + o * 4;
            uint32_t s = sbase + (uint32_t)(row * FSTRIDE + o * 4) * 4;
            cpasync16(s, g);
        }
        cp_commit();
    };

    float2 acc[CPT][K_];
    #pragma unroll
    for (int j = 0; j < CPT; j++)
        #pragma unroll
        for (int k = 0; k < K_; k++) acc[j][k] = make_float2(0.f, 0.f);

    issue_chunk(0);
    issue_chunk(1);
    issue_chunk(2);

    #pragma unroll 1
    for (int ch = 0; ch < NCH; ch++) {
        const int rem = NCH - 1 - ch;
        if (rem >= 3)      { issue_chunk(ch + 3); cp_wait<3>(); }
        else if (rem == 2) { cp_wait<2>(); }
        else if (rem == 1) { cp_wait<1>(); }
        else               { cp_wait<0>(); }
        __syncthreads();   // chunk ch (and masks on first iter) visible to all

        const float* cur = s_f + (ch & (NBUF - 1)) * SM_FEAT_WORDS;

        #pragma unroll
        for (int p = 0; p < CHUNK / 4; p++) {   // two float4-positions per chunk
            float4 v[CPT];
            #pragma unroll
            for (int j = 0; j < CPT; j++) {
                int row = tid + j * TPB;
                v[j] = *reinterpret_cast<const float4*>(cur + row * FSTRIDE + p * 4);
            }
            const float* mptr = s_m + ch * CHUNK + p * 4;
            #pragma unroll
            for (int k = 0; k < K_; k++) {
                float4 m4 = *reinterpret_cast<const float4*>(mptr + k * HW_);  // broadcast
                float2 mlo = make_float2(m4.x, m4.y);
                float2 mhi = make_float2(m4.z, m4.w);
                #pragma unroll
                for (int j = 0; j < CPT; j++) {
                    ffma2(acc[j][k], mlo, make_float2(v[j].x, v[j].y));
                    ffma2(acc[j][k], mhi, make_float2(v[j].z, v[j].w));
                }
            }
        }
        __syncthreads();   // all reads of cur done before its buffer is refilled
    }

    // ---- epilogue: mean, max over k, write both halves ----
    const float inv = 1.0f / (float)HW_;
    #pragma unroll
    for (int j = 0; j < CPT; j++) {
        const int c = cbase + tid + j * TPB;
        float mx = -3.402823466e+38f;
        #pragma unroll
        for (int k = 0; k < K_; k++) {
            float s = acc[j][k].x + acc[j][k].y;
            mx = fmaxf(mx, s);
        }
        const size_t orow = (size_t)b * (2 * C_);
        out[orow + C_ + c] = mx * inv;
        out[orow + c]      = pgf[(size_t)b * C_ + c];
    }
}

extern "C" void kernel_launch(void* const* d_in, const int* in_sizes, int n_in,
                              void* d_out, int out_size)
{
    const float* feat  = (const float*)d_in[0];
    const float* masks = (const float*)d_in[1];
    const float* pgf   = (const float*)d_in[2];
    float*       out   = (float*)d_out;

    cudaFuncSetAttribute(pgfa_kernel,
                         cudaFuncAttributeMaxDynamicSharedMemorySize,
                         SM_TOTAL_BYTES);

    dim3 grid(C_ / CTILE, B_);   // (4, 256)
    pgfa_kernel<<<grid, TPB, SM_TOTAL_BYTES>>>(feat, masks, pgf, out);
}

// round 6
// speedup vs baseline: 1.3480x; 1.3115x over previous
#include <cuda_runtime.h>
#include <cstdint>
#include <cfloat>

#define B_     256
#define C_     2048
#define K_     18        // landmarks (GEMM N)
#define HW_    192       // GEMM K
#define TPB    256
#define ROWS   256       // c-rows per CTA (GEMM M tile)
#define NPAD   24        // N padded to 3x8
#define NT     3         // n-tiles of 8
#define STAGE_K 16       // K per pipeline stage
#define NSTG   (HW_/STAGE_K)   // 12
#define NBUF   4
#define ASTRIDE 20       // feat smem row stride (16 data + 4 pad) -> conflict-free
#define BSTRIDE 196      // mask smem row stride (192 data + 4 pad) -> conflict-free

#define SM_B_WORDS (NPAD*BSTRIDE)            // 4704
#define SM_A_WORDS (ROWS*ASTRIDE)            // 5120 per buffer
#define SMEM_TOTAL ((SM_B_WORDS + NBUF*SM_A_WORDS)*4)   // 100,736 B

__device__ __forceinline__ uint32_t s2u(const void* p) {
    uint32_t a;
    asm("{ .reg .u64 t; cvta.to.shared.u64 t, %1; cvt.u32.u64 %0, t; }" : "=r"(a) : "l"(p));
    return a;
}
__device__ __forceinline__ void cpasync16(uint32_t s, const void* g) {
    asm volatile("cp.async.cg.shared.global [%0], [%1], 16;" :: "r"(s), "l"(g));
}
__device__ __forceinline__ void cp_commit() { asm volatile("cp.async.commit_group;" ::: "memory"); }
template <int N> __device__ __forceinline__ void cp_wait() {
    asm volatile("cp.async.wait_group %0;" :: "n"(N) : "memory");
}
__device__ __forceinline__ uint32_t f2tf32(float f) {
    uint32_t r;
    asm("cvt.rna.tf32.f32 %0, %1;" : "=r"(r) : "f"(f));
    return r;
}
__device__ __forceinline__ void mma_tf32(float& d0, float& d1, float& d2, float& d3,
                                         uint32_t a0, uint32_t a1, uint32_t a2, uint32_t a3,
                                         uint32_t b0, uint32_t b1) {
    asm volatile("mma.sync.aligned.m16n8k8.row.col.f32.tf32.tf32.f32 "
                 "{%0,%1,%2,%3}, {%4,%5,%6,%7}, {%8,%9}, {%0,%1,%2,%3};"
                 : "+f"(d0), "+f"(d1), "+f"(d2), "+f"(d3)
                 : "r"(a0), "r"(a1), "r"(a2), "r"(a3), "r"(b0), "r"(b1));
}
__device__ __forceinline__ float shfl_xor_max(float v, int m) {
    float r;
    asm volatile("shfl.sync.bfly.b32 %0, %1, %2, 0x1F, 0xFFFFFFFF;" : "=f"(r) : "f"(v), "r"(m));
    return fmaxf(v, r);
}

extern __shared__ float smem[];

__global__ __launch_bounds__(TPB, 2)
void pgfa_mma_kernel(const float* __restrict__ feat,
                     const float* __restrict__ masks,
                     const float* __restrict__ pgf,
                     float* __restrict__ out)
{
    float* s_b = smem;                 // [NPAD][BSTRIDE]
    float* s_a = smem + SM_B_WORDS;    // NBUF x [ROWS][ASTRIDE]

    const int tid  = threadIdx.x;
    const int wid  = tid >> 5;
    const int lane = tid & 31;
    const int gid  = lane >> 2;        // group id (0..7)
    const int tig  = lane & 3;         // thread-in-group
    const int b    = blockIdx.y;
    const int rowbase = blockIdx.x * ROWS;

    // ---- stage masks[b] as B [n][k] (natural layout = col-major B), pad n>=18 with 0 ----
    {
        const float* msrc = masks + (size_t)b * K_ * HW_;
        for (int i = tid; i < K_ * HW_; i += TPB) {
            int n = i / HW_, k = i - n * HW_;
            s_b[n * BSTRIDE + k] = msrc[i];
        }
        for (int i = tid; i < (NPAD - K_) * HW_; i += TPB) {
            int n = K_ + i / HW_, k = i % HW_;
            s_b[n * BSTRIDE + k] = 0.0f;
        }
    }

    const float* fbase = feat + ((size_t)b * C_ + rowbase) * HW_;
    const uint32_t sabase = s2u(s_a);

    // cp.async one stage: 256 rows x 16 floats = 1024 float4, 4 per thread
    auto issue_stage = [&](int s) {
        uint32_t sb = sabase + (uint32_t)(s & (NBUF - 1)) * (SM_A_WORDS * 4);
        const int k0 = s * STAGE_K;
        #pragma unroll
        for (int q = 0; q < 4; q++) {
            int flat = q * TPB + tid;
            int row  = flat >> 2, c4 = flat & 3;
            cpasync16(sb + (uint32_t)(row * ASTRIDE + c4 * 4) * 4,
                      fbase + (size_t)row * HW_ + k0 + c4 * 4);
        }
        cp_commit();
    };

    float d[2][NT][4];
    #pragma unroll
    for (int mt = 0; mt < 2; mt++)
        #pragma unroll
        for (int nt = 0; nt < NT; nt++)
            #pragma unroll
            for (int j = 0; j < 4; j++) d[mt][nt][j] = 0.0f;

    issue_stage(0); issue_stage(1); issue_stage(2);

    const int wbase = wid * 32;     // 32 rows per warp

    #pragma unroll 1
    for (int s = 0; s < NSTG; s++) {
        if (s + 3 < NSTG) issue_stage(s + 3);
        const int rem = NSTG - 1 - s;
        if (rem >= 3)      cp_wait<3>();
        else if (rem == 2) cp_wait<2>();
        else if (rem == 1) cp_wait<1>();
        else               cp_wait<0>();
        __syncthreads();

        const float* abuf = s_a + (s & (NBUF - 1)) * SM_A_WORDS;

        #pragma unroll
        for (int kc = 0; kc < 2; kc++) {               // two K=8 chunks per stage
            const int kl = kc * 8;
            const int kg = s * STAGE_K + kl;
            // B fragments (shared by both m-tiles)
            uint32_t bf[NT][2];
            #pragma unroll
            for (int nt = 0; nt < NT; nt++) {
                int n = nt * 8 + gid;
                bf[nt][0] = f2tf32(s_b[n * BSTRIDE + kg + tig]);
                bf[nt][1] = f2tf32(s_b[n * BSTRIDE + kg + tig + 4]);
            }
            #pragma unroll
            for (int mt = 0; mt < 2; mt++) {
                const int r = wbase + mt * 16;
                uint32_t a0 = f2tf32(abuf[(r + gid)     * ASTRIDE + kl + tig]);
                uint32_t a1 = f2tf32(abuf[(r + gid + 8) * ASTRIDE + kl + tig]);
                uint32_t a2 = f2tf32(abuf[(r + gid)     * ASTRIDE + kl + tig + 4]);
                uint32_t a3 = f2tf32(abuf[(r + gid + 8) * ASTRIDE + kl + tig + 4]);
                #pragma unroll
                for (int nt = 0; nt < NT; nt++)
                    mma_tf32(d[mt][nt][0], d[mt][nt][1], d[mt][nt][2], d[mt][nt][3],
                             a0, a1, a2, a3, bf[nt][0], bf[nt][1]);
            }
        }
        __syncthreads();
    }

    // ---- pgf copy half (coalesced) ----
    const size_t orow = (size_t)b * (2 * C_);
    out[orow + rowbase + tid] = pgf[(size_t)b * C_ + rowbase + tid];

    // ---- epilogue: max over n (exclude pad n>=18), scale 1/HW, store ----
    const float inv = 1.0f / (float)HW_;
    #pragma unroll
    for (int mt = 0; mt < 2; mt++) {
        float m0 = -FLT_MAX, m1 = -FLT_MAX;
        #pragma unroll
        for (int nt = 0; nt < NT; nt++)
            #pragma unroll
            for (int j = 0; j < 2; j++) {
                int n = nt * 8 + tig * 2 + j;
                if (n < K_) {
                    m0 = fmaxf(m0, d[mt][nt][j]);
                    m1 = fmaxf(m1, d[mt][nt][2 + j]);
                }
            }
        m0 = shfl_xor_max(m0, 1); m0 = shfl_xor_max(m0, 2);
        m1 = shfl_xor_max(m1, 1); m1 = shfl_xor_max(m1, 2);
        if (tig == 0) {
            int r = rowbase + wbase + mt * 16 + gid;
            out[orow + C_ + r]     = m0 * inv;
            out[orow + C_ + r + 8] = m1 * inv;
        }
    }
}

extern "C" void kernel_launch(void* const* d_in, const int* in_sizes, int n_in,
                              void* d_out, int out_size)
{
    const float* feat  = (const float*)d_in[0];
    const float* masks = (const float*)d_in[1];
    const float* pgf   = (const float*)d_in[2];
    float*       out   = (float*)d_out;

    cudaFuncSetAttribute(pgfa_mma_kernel,
                         cudaFuncAttributeMaxDynamicSharedMemorySize, SMEM_TOTAL);

    dim3 grid(C_ / ROWS, B_);    // (8, 256)
    pgfa_mma_kernel<<<grid, TPB, SMEM_TOTAL>>>(feat, masks, pgf, out);
}

// round 7
// speedup vs baseline: 1.5375x; 1.1405x over previous
#include <cuda_runtime.h>
#include <cstdint>
#include <cfloat>

#define B_     256
#define C_     2048
#define K_     18        // landmarks (GEMM N)
#define HW_    192       // GEMM K
#define TPB    256
#define ROWS   256       // c-rows per CTA (GEMM M tile)
#define NPAD   24        // N padded to 3x8
#define NT     3
#define STAGE_K 16
#define NSTG   (HW_/STAGE_K)   // 12
#define NBUF   3
#define BSTRIDE 196      // 196 mod 32 = 4 -> B frag LDS conflict-free

#define SM_B_WORDS (NPAD*BSTRIDE)            // 4704
#define SM_A_WORDS (ROWS*STAGE_K)            // 4096 per buffer (swizzled, no pad)
#define SMEM_TOTAL ((SM_B_WORDS + NBUF*SM_A_WORDS)*4)   // 67,968 B

// quad swizzle: quad q of row r lives at q ^ ((r>>1)&3)
__device__ __forceinline__ int aswz(int row, int q) { return q ^ ((row >> 1) & 3); }

__device__ __forceinline__ uint32_t s2u(const void* p) {
    uint32_t a;
    asm("{ .reg .u64 t; cvta.to.shared.u64 t, %1; cvt.u32.u64 %0, t; }" : "=r"(a) : "l"(p));
    return a;
}
__device__ __forceinline__ void cpasync16(uint32_t s, const void* g) {
    asm volatile("cp.async.cg.shared.global [%0], [%1], 16;" :: "r"(s), "l"(g));
}
__device__ __forceinline__ void cp_commit() { asm volatile("cp.async.commit_group;" ::: "memory"); }
template <int N> __device__ __forceinline__ void cp_wait() {
    asm volatile("cp.async.wait_group %0;" :: "n"(N) : "memory");
}
__device__ __forceinline__ uint32_t f2tf32(float f) {
    uint32_t r;
    asm("cvt.rna.tf32.f32 %0, %1;" : "=r"(r) : "f"(f));
    return r;
}
__device__ __forceinline__ void mma_tf32(float& d0, float& d1, float& d2, float& d3,
                                         uint32_t a0, uint32_t a1, uint32_t a2, uint32_t a3,
                                         uint32_t b0, uint32_t b1) {
    asm volatile("mma.sync.aligned.m16n8k8.row.col.f32.tf32.tf32.f32 "
                 "{%0,%1,%2,%3}, {%4,%5,%6,%7}, {%8,%9}, {%0,%1,%2,%3};"
                 : "+f"(d0), "+f"(d1), "+f"(d2), "+f"(d3)
                 : "r"(a0), "r"(a1), "r"(a2), "r"(a3), "r"(b0), "r"(b1));
}
__device__ __forceinline__ float shfl_xor_max(float v, int m) {
    float r;
    asm volatile("shfl.sync.bfly.b32 %0, %1, %2, 0x1F, 0xFFFFFFFF;" : "=f"(r) : "f"(v), "r"(m));
    return fmaxf(v, r);
}

extern __shared__ float smem[];

__global__ __launch_bounds__(TPB, 3)
void pgfa_mma_kernel(const float* __restrict__ feat,
                     const float* __restrict__ masks,
                     const float* __restrict__ pgf,
                     float* __restrict__ out)
{
    float* s_b = smem;                 // [NPAD][BSTRIDE]
    float* s_a = smem + SM_B_WORDS;    // NBUF x [ROWS][16] quad-swizzled

    const int tid  = threadIdx.x;
    const int wid  = tid >> 5;
    const int lane = tid & 31;
    const int gid  = lane >> 2;
    const int tig  = lane & 3;
    const int b    = blockIdx.y;
    const int rowbase = blockIdx.x * ROWS;

    // ---- stage masks[b] as B [n][k], pad n>=18 with 0 ----
    {
        const float* msrc = masks + (size_t)b * K_ * HW_;
        for (int i = tid; i < K_ * HW_; i += TPB) {
            int n = i / HW_, k = i - n * HW_;
            s_b[n * BSTRIDE + k] = msrc[i];
        }
        for (int i = tid; i < (NPAD - K_) * HW_; i += TPB) {
            int n = K_ + i / HW_, k = i % HW_;
            s_b[n * BSTRIDE + k] = 0.0f;
        }
    }

    const float* fbase = feat + ((size_t)b * C_ + rowbase) * HW_;
    const uint32_t sabase = s2u(s_a);

    // one stage: 256 rows x 16 floats = 1024 float4, 4 per thread, quad-swizzled
    auto issue_stage = [&](int s) {
        uint32_t sb = sabase + (uint32_t)((s % NBUF) * SM_A_WORDS) * 4;
        const int k0 = s * STAGE_K;
        #pragma unroll
        for (int q = 0; q < 4; q++) {
            int flat = q * TPB + tid;
            int row  = flat >> 2, c4 = flat & 3;
            cpasync16(sb + (uint32_t)(row * STAGE_K + aswz(row, c4) * 4) * 4,
                      fbase + (size_t)row * HW_ + k0 + c4 * 4);
        }
        cp_commit();
    };

    float d[2][NT][4];
    #pragma unroll
    for (int mt = 0; mt < 2; mt++)
        #pragma unroll
        for (int nt = 0; nt < NT; nt++)
            #pragma unroll
            for (int j = 0; j < 4; j++) d[mt][nt][j] = 0.0f;

    issue_stage(0); issue_stage(1);

    const int wbase = wid * 32;

    #pragma unroll 1
    for (int s = 0; s < NSTG; s++) {
        if (s < NSTG - 1) cp_wait<1>();   // stage s complete (groups s, s+1 outstanding)
        else              cp_wait<0>();   // last stage: only group s outstanding
        __syncthreads();                  // all warps done with stage s-1's buffer
        if (s + 2 < NSTG) issue_stage(s + 2);   // overwrites buffer (s-1)%3: safe

        const float* abuf = s_a + (s % NBUF) * SM_A_WORDS;

        #pragma unroll
        for (int kc = 0; kc < 2; kc++) {
            const int kl = kc * 8;
            const int kg = s * STAGE_K + kl;
            uint32_t bf[NT][2];
            #pragma unroll
            for (int nt = 0; nt < NT; nt++) {
                int n = nt * 8 + gid;
                bf[nt][0] = f2tf32(s_b[n * BSTRIDE + kg + tig]);
                bf[nt][1] = f2tf32(s_b[n * BSTRIDE + kg + tig + 4]);
            }
            #pragma unroll
            for (int mt = 0; mt < 2; mt++) {
                const int r0 = wbase + mt * 16 + gid;
                const int r1 = r0 + 8;
                const int kq0 = kl >> 2;          // quad of kl+tig
                uint32_t a0 = f2tf32(abuf[r0 * STAGE_K + aswz(r0, kq0)     * 4 + tig]);
                uint32_t a1 = f2tf32(abuf[r1 * STAGE_K + aswz(r1, kq0)     * 4 + tig]);
                uint32_t a2 = f2tf32(abuf[r0 * STAGE_K + aswz(r0, kq0 + 1) * 4 + tig]);
                uint32_t a3 = f2tf32(abuf[r1 * STAGE_K + aswz(r1, kq0 + 1) * 4 + tig]);
                #pragma unroll
                for (int nt = 0; nt < NT; nt++)
                    mma_tf32(d[mt][nt][0], d[mt][nt][1], d[mt][nt][2], d[mt][nt][3],
                             a0, a1, a2, a3, bf[nt][0], bf[nt][1]);
            }
        }
    }

    // ---- pgf copy half (coalesced) ----
    const size_t orow = (size_t)b * (2 * C_);
    out[orow + rowbase + tid] = pgf[(size_t)b * C_ + rowbase + tid];

    // ---- epilogue: max over n (exclude pad), scale 1/HW, store ----
    const float inv = 1.0f / (float)HW_;
    #pragma unroll
    for (int mt = 0; mt < 2; mt++) {
        float m0 = -FLT_MAX, m1 = -FLT_MAX;
        #pragma unroll
        for (int nt = 0; nt < NT; nt++)
            #pragma unroll
            for (int j = 0; j < 2; j++) {
                int n = nt * 8 + tig * 2 + j;
                if (n < K_) {
                    m0 = fmaxf(m0, d[mt][nt][j]);
                    m1 = fmaxf(m1, d[mt][nt][2 + j]);
                }
            }
        m0 = shfl_xor_max(m0, 1); m0 = shfl_xor_max(m0, 2);
        m1 = shfl_xor_max(m1, 1); m1 = shfl_xor_max(m1, 2);
        if (tig == 0) {
            int r = rowbase + wbase + mt * 16 + gid;
            out[orow + C_ + r]     = m0 * inv;
            out[orow + C_ + r + 8] = m1 * inv;
        }
    }
}

extern "C" void kernel_launch(void* const* d_in, const int* in_sizes, int n_in,
                              void* d_out, int out_size)
{
    const float* feat  = (const float*)d_in[0];
    const float* masks = (const float*)d_in[1];
    const float* pgf   = (const float*)d_in[2];
    float*       out   = (float*)d_out;

    cudaFuncSetAttribute(pgfa_mma_kernel,
                         cudaFuncAttributeMaxDynamicSharedMemorySize, SMEM_TOTAL);

    dim3 grid(C_ / ROWS, B_);    // (8, 256)
    pgfa_mma_kernel<<<grid, TPB, SMEM_TOTAL>>>(feat, masks, pgf, out);
}